// round 14
// baseline (speedup 1.0000x reference)
#include <cuda_runtime.h>
#include <cuda_bf16.h>
#include <math.h>
#include <stdint.h>

#define HW    784
#define NPIX  12544          // 16*28*28
#define MM    8192
#define FBIG  3.402823466e38f

// ---------------------------------------------------------------------------
// PTX helpers (sm_80+ family: ldmatrix / mma.sync / cp.async)
// ---------------------------------------------------------------------------
__device__ __forceinline__ uint32_t smem_u32(const void* p) {
    uint32_t a;
    asm("{ .reg .u64 t; cvta.to.shared.u64 t, %1; cvt.u32.u64 %0, t; }" : "=r"(a) : "l"(p));
    return a;
}
__device__ __forceinline__ void ldsm4(uint32_t* r, uint32_t a) {
    asm volatile("ldmatrix.sync.aligned.m8n8.x4.shared.b16 {%0,%1,%2,%3}, [%4];"
                 : "=r"(r[0]), "=r"(r[1]), "=r"(r[2]), "=r"(r[3]) : "r"(a));
}
__device__ __forceinline__ void mma16816(float* c, const uint32_t* a, const uint32_t* b) {
    asm volatile("mma.sync.aligned.m16n8k16.row.col.f32.bf16.bf16.f32 "
                 "{%0,%1,%2,%3},{%4,%5,%6,%7},{%8,%9},{%0,%1,%2,%3};"
                 : "+f"(c[0]), "+f"(c[1]), "+f"(c[2]), "+f"(c[3])
                 : "r"(a[0]), "r"(a[1]), "r"(a[2]), "r"(a[3]), "r"(b[0]), "r"(b[1]));
}
__device__ __forceinline__ void cpasync16(uint32_t dst, const void* src) {
    asm volatile("cp.async.cg.shared.global [%0], [%1], 16;" :: "r"(dst), "l"(src) : "memory");
}
#define CP_COMMIT() asm volatile("cp.async.commit_group;" ::: "memory")
#define CP_WAIT1()  asm volatile("cp.async.wait_group 1;"  ::: "memory")
#define CP_WAIT0()  asm volatile("cp.async.wait_group 0;"  ::: "memory")

// ---------------------------------------------------------------------------
// device scratch
// ---------------------------------------------------------------------------
__device__ float g_mnorm[2][MM];
__device__ float g_qnorm[2][NPIX];
__device__ float g_maha[2][NPIX];
__device__ float g_part[3][NPIX * 5];
__device__ float g_mahav[2][256];
__device__ float g_mahas0[2];
__device__ __align__(128) __nv_bfloat16 g_memb2[MM * 128];
__device__ __align__(128) __nv_bfloat16 g_memb3[MM * 256];
__device__ __align__(128) __nv_bfloat16 g_icovb2[256 * 128];
__device__ __align__(128) __nv_bfloat16 g_icovb3[256 * 256];

// ---------------- prep bodies (dispatched from one fat kernel) ----------------
template <int C, int LAYER>
__device__ __forceinline__ void prep_memb_body(const float* __restrict__ mem, int blk) {
    int i = blk * 256 + threadIdx.x;             // one i = 8 elements
    const float4 v0 = *reinterpret_cast<const float4*>(mem + (size_t)i * 8);
    const float4 v1 = *reinterpret_cast<const float4*>(mem + (size_t)i * 8 + 4);
    float s = v0.x * v0.x + v0.y * v0.y + v0.z * v0.z + v0.w * v0.w
            + v1.x * v1.x + v1.y * v1.y + v1.z * v1.z + v1.w * v1.w;
    __nv_bfloat16 t[8];
    t[0] = __float2bfloat16_rn(v0.x); t[1] = __float2bfloat16_rn(v0.y);
    t[2] = __float2bfloat16_rn(v0.z); t[3] = __float2bfloat16_rn(v0.w);
    t[4] = __float2bfloat16_rn(v1.x); t[5] = __float2bfloat16_rn(v1.y);
    t[6] = __float2bfloat16_rn(v1.z); t[7] = __float2bfloat16_rn(v1.w);
    __nv_bfloat16* dst = ((LAYER == 0) ? g_memb2 : g_memb3) + (size_t)i * 8;
    *reinterpret_cast<uint4*>(dst) = *reinterpret_cast<const uint4*>(t);
    const int SEG = C / 8;                       // 16 (C=128) or 32 (C=256)
#pragma unroll
    for (int o = SEG / 2; o; o >>= 1) s += __shfl_down_sync(0xffffffffu, s, o, SEG);
    if ((threadIdx.x & (SEG - 1)) == 0) g_mnorm[LAYER][i / SEG] = s;
}

template <int C, int LAYER>
__device__ __forceinline__ void prep_icov_body(const float* __restrict__ icov, int blk) {
    const int PER = C / 8;
    int i = blk * 256 + threadIdx.x;
    if (i >= 256 * PER) return;
    int col = i / PER, k0 = (i - col * PER) * 8;
    __nv_bfloat16 t[8];
    if (col < C) {
        const float* src = icov + (size_t)col * C + k0;
#pragma unroll
        for (int j = 0; j < 8; ++j) t[j] = __float2bfloat16_rn(src[j]);
    } else {
#pragma unroll
        for (int j = 0; j < 8; ++j) t[j] = __float2bfloat16_rn(0.f);
    }
    __nv_bfloat16* dst = ((LAYER == 0) ? g_icovb2 : g_icovb3) + (size_t)col * C + k0;
    *reinterpret_cast<uint4*>(dst) = *reinterpret_cast<const uint4*>(t);
}

template <int C, int LAYER>
__device__ __forceinline__ void prep_mahav_body(const float* __restrict__ icov,
                                                const float* __restrict__ mean,
                                                float* smean, float* red) {
    int c = threadIdx.x;                     // 256 threads
    if (c < C) smean[c] = mean[c];
    __syncthreads();
    float v = 0.f;
    if (c < C)
        for (int k = 0; k < C; ++k) v = fmaf(icov[(size_t)k * C + c], smean[k], v);
    g_mahav[LAYER][c] = (c < C) ? v : 0.f;
    red[c] = (c < C) ? v * smean[c] : 0.f;
    __syncthreads();
    for (int s = 128; s > 0; s >>= 1) {
        if (c < s) red[c] += red[c + s];
        __syncthreads();
    }
    if (c == 0) g_mahas0[LAYER] = red[0];
}

__global__ void prep_all_kernel(const float* __restrict__ mem2, const float* __restrict__ mem3,
                                const float* __restrict__ icov2, const float* __restrict__ icov3,
                                const float* __restrict__ mean2, const float* __restrict__ mean3) {
    __shared__ float smean[256];
    __shared__ float red[256];
    int bx = blockIdx.x;
    if (bx < 512)        prep_memb_body<128, 0>(mem2, bx);
    else if (bx < 1536)  prep_memb_body<256, 1>(mem3, bx - 512);
    else if (bx < 1552)  prep_icov_body<128, 0>(icov2, bx - 1536);
    else if (bx < 1584)  prep_icov_body<256, 1>(icov3, bx - 1552);
    else if (bx == 1584) prep_mahav_body<128, 0>(icov2, mean2, smean, red);
    else                 prep_mahav_body<256, 1>(icov3, mean3, smean, red);
}

// ---------------- sorted-5 insert (ascending, t[4] largest) ----------------
__device__ __forceinline__ void ins5(float* t, float v) {
    if (v < t[4]) {
#pragma unroll
        for (int u = 0; u < 5; ++u) {
            float c = t[u];
            float lo = fminf(c, v), hi = fmaxf(c, v);
            t[u] = lo; v = hi;
        }
    }
}

// ---------------------------------------------------------------------------
// knn GEMM body: 64 rows x MSPAN cols via mma.sync, fused top-5 + maha
// block = 256 threads = 8 warps (2 row-bands x 4 col-warps), warp tile 32x64
// stage = 256 cols x 64k (32KB), ring-2, 2 CTAs/SM
// ---------------------------------------------------------------------------
template <int C, int LAYER, int SPLIT, int MSPAN, int DO_MAHA>
__device__ __forceinline__ void knn_body(const float* __restrict__ q,
                                         const __nv_bfloat16* __restrict__ gb,
                                         const __nv_bfloat16* __restrict__ icb,
                                         int colbase, char* sm) {
    constexpr int KTPC = C / 64;                 // k-tiles (of 64) per chunk
    constexpr int NSTN = (MSPAN / 256) * KTPC;   // normal stages (=64)
    constexpr int NSTT = NSTN + (DO_MAHA ? KTPC : 0);
    char* smA   = sm;                            // 64 x C bf16, swizzled
    char* smB   = sm + C * 128;                  // 2 x 32KB ring
    float* qp   = (float*)(sm + C * 128 + 65536);    // 16 x 64
    float* mh   = qp + 1024;                         // 64 x 16 maha partials

    const int tid  = threadIdx.x;
    const int lane = tid & 31, wid = tid >> 5;
    const int wr = wid >> 2, wc = wid & 3;
    const int row0 = blockIdx.x * 64;

    const uint32_t uA  = smem_u32(smA);
    const uint32_t uBb = smem_u32(smB);

    auto issue = [&](int s) {
        const __nv_bfloat16* srcb;
        if (s < NSTN) {
            const int ch = s / KTPC, kt = s - ch * KTPC;
            srcb = gb + (size_t)(colbase + ch * 256) * C + kt * 64;
        } else {
            srcb = icb + (size_t)(s - NSTN) * 64;        // icov chunk
        }
        const uint32_t db = uBb + (s & 1) * 32768;
#pragma unroll
        for (int j = 0; j < 8; ++j) {
            int id = tid + 256 * j;
            int ncol = id >> 3, kk = (id & 7) * 8;
            cpasync16(db + ncol * 128 + ((kk * 2) ^ ((ncol & 7) << 4)),
                      srcb + (size_t)ncol * C + kk);
        }
        CP_COMMIT();
    };

    issue(0); issue(1);                          // B streams during A gather

    // ---- A load: float4 along pixels (784%4==0 -> never crosses image) ----
    {
        const int r4 = (tid & 15) * 4;           // 4-row group (16 groups = 64 rows)
        const int cg = tid >> 4;                 // 16 channel groups
        float qn[4] = {0.f, 0.f, 0.f, 0.f};
        const int n = row0 + r4, b = n / HW, p = n - b * HW;
#pragma unroll 4
        for (int c = cg; c < C; c += 16) {
            const float4 v = *reinterpret_cast<const float4*>(q + ((size_t)b * C + c) * HW + p);
            qn[0] = fmaf(v.x, v.x, qn[0]); qn[1] = fmaf(v.y, v.y, qn[1]);
            qn[2] = fmaf(v.z, v.z, qn[2]); qn[3] = fmaf(v.w, v.w, qn[3]);
            const float vv[4] = {v.x, v.y, v.z, v.w};
#pragma unroll
            for (int j = 0; j < 4; ++j)
                *reinterpret_cast<__nv_bfloat16*>(smA + (r4 + j) * (C * 2) +
                    ((c * 2) ^ (((r4 + j) & 7) << 4))) = __float2bfloat16_rn(vv[j]);
        }
#pragma unroll
        for (int j = 0; j < 4; ++j) qp[cg * 64 + r4 + j] = qn[j];
    }
    __syncthreads();

    // ---- fragment address bases ----
    const uint32_t sw = (lane & 7) << 4;
    uint32_t aRow[2];
#pragma unroll
    for (int mi = 0; mi < 2; ++mi)
        aRow[mi] = uA + (wr * 32 + mi * 16 + (lane & 15)) * (C * 2);
    const uint32_t aKx = (lane >> 4) << 4;
    const uint32_t bCol = (uint32_t)(wc * 64 + ((lane >> 4) << 3) + (lane & 7));
    const uint32_t bKh  = ((lane >> 3) & 1) << 4;

    float acc[2][8][4];
#pragma unroll
    for (int mi = 0; mi < 2; ++mi)
#pragma unroll
        for (int ni = 0; ni < 8; ++ni)
#pragma unroll
            for (int e = 0; e < 4; ++e) acc[mi][ni][e] = 0.f;
    float t5[2][2][5];
#pragma unroll
    for (int mi = 0; mi < 2; ++mi)
#pragma unroll
        for (int h = 0; h < 2; ++h)
#pragma unroll
            for (int s = 0; s < 5; ++s) t5[mi][h][s] = FBIG;
    float mm[2][2] = {{0.f, 0.f}, {0.f, 0.f}};   // maha partials

    auto qrd = [&](int rl, int c) -> float {
        int cc = (c < C) ? c : (C - 1);
        uint16_t hbits = *reinterpret_cast<const uint16_t*>(
            smA + rl * (C * 2) + ((cc * 2) ^ ((rl & 7) << 4)));
        __nv_bfloat16 bh = *reinterpret_cast<__nv_bfloat16*>(&hbits);
        return __bfloat162float(bh);
    };

    for (int s = 0; s < NSTT; ++s) {
        if (s == NSTT - 1) CP_WAIT0(); else CP_WAIT1();
        __syncthreads();                     // stage s data visible to all
        const int kt = s % KTPC;
        const uint32_t db = uBb + (s & 1) * 32768;
#pragma unroll
        for (int ks = 0; ks < 4; ++ks) {
            uint32_t a[2][4];
            const uint32_t kbA = (uint32_t)(kt * 128 + ks * 32) + aKx;
#pragma unroll
            for (int mi = 0; mi < 2; ++mi) ldsm4(a[mi], aRow[mi] + (kbA ^ sw));
            const uint32_t kbB = (uint32_t)(ks * 32) + bKh;
#pragma unroll
            for (int nj = 0; nj < 4; ++nj) {
                uint32_t b[4];
                ldsm4(b, db + (bCol + nj * 16) * 128 + (kbB ^ sw));
#pragma unroll
                for (int mi = 0; mi < 2; ++mi) {
                    mma16816(acc[mi][nj * 2],     a[mi], b);
                    mma16816(acc[mi][nj * 2 + 1], a[mi], b + 2);
                }
            }
        }
        if (kt == KTPC - 1) {
            if (s < NSTN) {                  // normal chunk: fold into top-5
                const int ch = s / KTPC;
                const int cb = colbase + ch * 256 + wc * 64 + 2 * (lane & 3);
#pragma unroll
                for (int ni = 0; ni < 8; ++ni) {
                    const float mn0 = __ldg(&g_mnorm[LAYER][cb + ni * 8]);
                    const float mn1 = __ldg(&g_mnorm[LAYER][cb + ni * 8 + 1]);
#pragma unroll
                    for (int mi = 0; mi < 2; ++mi) {
                        ins5(t5[mi][0], fmaf(-2.f, acc[mi][ni][0], mn0));
                        ins5(t5[mi][0], fmaf(-2.f, acc[mi][ni][1], mn1));
                        ins5(t5[mi][1], fmaf(-2.f, acc[mi][ni][2], mn0));
                        ins5(t5[mi][1], fmaf(-2.f, acc[mi][ni][3], mn1));
                        acc[mi][ni][0] = 0.f; acc[mi][ni][1] = 0.f;
                        acc[mi][ni][2] = 0.f; acc[mi][ni][3] = 0.f;
                    }
                }
            } else if (DO_MAHA) {            // icov chunk: maha partials
                const int mcb = wc * 64 + 2 * (lane & 3);
#pragma unroll
                for (int ni = 0; ni < 8; ++ni) {
                    const int c0 = mcb + ni * 8, c1 = c0 + 1;
                    const float v0 = __ldg(&g_mahav[LAYER][c0]);
                    const float v1 = __ldg(&g_mahav[LAYER][c1]);
#pragma unroll
                    for (int mi = 0; mi < 2; ++mi) {
                        const int rl0 = wr * 32 + mi * 16 + (lane >> 2);
                        const int rl1 = rl0 + 8;
                        mm[mi][0] += (acc[mi][ni][0] - 2.f * v0) * qrd(rl0, c0)
                                   + (acc[mi][ni][1] - 2.f * v1) * qrd(rl0, c1);
                        mm[mi][1] += (acc[mi][ni][2] - 2.f * v0) * qrd(rl1, c0)
                                   + (acc[mi][ni][3] - 2.f * v1) * qrd(rl1, c1);
                    }
                }
            }
        }
        __syncthreads();                     // all warps done reading slot s&1
        if (s + 2 < NSTT) issue(s + 2);      // refill freed slot
    }

    // ---- per-row merges (smem aliasing: A/B region now free) ----
    float* mg = (float*)sm;                  // 64 x 80 floats
#pragma unroll
    for (int mi = 0; mi < 2; ++mi)
#pragma unroll
        for (int h = 0; h < 2; ++h) {
            int rl = wr * 32 + mi * 16 + (lane >> 2) + 8 * h;
            int slot = wc * 4 + (lane & 3);
#pragma unroll
            for (int u = 0; u < 5; ++u) mg[rl * 80 + slot * 5 + u] = t5[mi][h][u];
            if (DO_MAHA) mh[rl * 16 + slot] = mm[mi][h];
        }
    __syncthreads();
    if (tid < 64) {
        float* c = mg + tid * 80;
        for (int it = 0; it < 5; ++it) {
            float mv = FBIG; int mi2 = 0;
            for (int e = 0; e < 80; ++e) { float v = c[e]; if (v < mv) { mv = v; mi2 = e; } }
            c[mi2] = FBIG;
            g_part[SPLIT][(size_t)(row0 + tid) * 5 + it] = mv;
        }
        if (SPLIT <= 1) {
            float qn = 0.f;
#pragma unroll
            for (int k = 0; k < 16; ++k) qn += qp[k * 64 + tid];
            g_qnorm[LAYER][row0 + tid] = qn;
        }
        if (DO_MAHA) {
            float s = __ldg(&g_mahas0[LAYER]);
#pragma unroll
            for (int e = 0; e < 16; ++e) s += mh[tid * 16 + e];
            g_maha[LAYER][row0 + tid] = sqrtf(fmaxf(s, 1e-12f));
        }
    }
}

__global__ __launch_bounds__(256, 2)
void knn_mma_kernel(const float* __restrict__ q2, const float* __restrict__ q3) {
    extern __shared__ char sm[];
    if (blockIdx.y == 0)
        knn_body<128, 0, 0, 8192, 1>(q2, g_memb2, g_icovb2, 0,    sm);
    else if (blockIdx.y == 1)
        knn_body<256, 1, 1, 4096, 1>(q3, g_memb3, g_icovb3, 0,    sm);
    else
        knn_body<256, 1, 2, 4096, 0>(q3, g_memb3, g_icovb3, 4096, sm);
}

// ---------------- fused finalize + combine + per-image top-10 ----------------
// grid = 16 (one block per image), 256 threads
__global__ void finalize_topk_kernel(float* __restrict__ out) {
    __shared__ float cmb[HW];
    const int b = blockIdx.x, tid = threadIdx.x;
    for (int p = tid; p < HW; p += 256) {
        const int n = b * HW + p;
        float knn0, knn1;
        {
            float qn = g_qnorm[0][n], sum = 0.f;
#pragma unroll
            for (int t = 0; t < 5; ++t)
                sum += sqrtf(fmaxf(g_part[0][(size_t)n * 5 + t] + qn, 1e-12f));
            knn0 = sum * 0.2f;
        }
        {
            float v[10];
#pragma unroll
            for (int t = 0; t < 5; ++t) {
                v[t]     = g_part[1][(size_t)n * 5 + t];
                v[5 + t] = g_part[2][(size_t)n * 5 + t];
            }
            float qn = g_qnorm[1][n], sum = 0.f;
            for (int it = 0; it < 5; ++it) {
                float mv = FBIG; int mi = 0;
#pragma unroll
                for (int e = 0; e < 10; ++e) if (v[e] < mv) { mv = v[e]; mi = e; }
                v[mi] = FBIG;
                sum += sqrtf(fmaxf(mv + qn, 1e-12f));
            }
            knn1 = sum * 0.2f;
        }
        float m2 = 0.5f * (knn0 + g_maha[0][n]);
        float m3 = 0.5f * (knn1 + g_maha[1][n]);
        float cm = 0.5f * (m2 + m3);
        out[16 + n]            = cm;
        out[16 + NPIX + n]     = m2;
        out[16 + 2 * NPIX + n] = m3;
        cmb[p] = cm;
    }
    __syncthreads();
    if (tid < 32) {                          // warp 0: top-10 over smem
        const int lane = tid;
        float t[10];
#pragma unroll
        for (int s = 0; s < 10; ++s) t[s] = -FBIG;   // ascending, t[0]=min kept
        for (int p = lane; p < HW; p += 32) {
            float v = cmb[p];
            if (v > t[0]) {
                t[0] = v;
#pragma unroll
                for (int s = 0; s < 9; ++s) {
                    float a = t[s], c = t[s + 1];
                    t[s] = fminf(a, c); t[s + 1] = fmaxf(a, c);
                }
            }
        }
        int pos = 9;
        float sum = 0.f;
        for (int it = 0; it < 10; ++it) {
            float best = (pos >= 0) ? t[pos] : -FBIG;
            int   bl   = lane;
#pragma unroll
            for (int o = 16; o; o >>= 1) {
                float ov = __shfl_xor_sync(0xffffffffu, best, o);
                int   ol = __shfl_xor_sync(0xffffffffu, bl, o);
                if (ov > best || (ov == best && ol < bl)) { best = ov; bl = ol; }
            }
            sum += best;
            if (lane == bl) --pos;
        }
        if (lane == 0) out[b] = sum * 0.1f;
    }
}

// ---------------- launch ----------------
extern "C" void kernel_launch(void* const* d_in, const int* in_sizes, int n_in,
                              void* d_out, int out_size) {
    const float* q2    = (const float*)d_in[0];
    const float* q3    = (const float*)d_in[1];
    const float* mem2  = (const float*)d_in[2];
    const float* mem3  = (const float*)d_in[3];
    const float* mean2 = (const float*)d_in[4];
    const float* mean3 = (const float*)d_in[5];
    const float* icov2 = (const float*)d_in[6];
    const float* icov3 = (const float*)d_in[7];
    float* out = (float*)d_out;

    // dyn smem (C=256): A 32KB + B ring 2x32KB + qp 4KB + mh 4KB = 106496
    const int SMEM = 256 * 128 + 2 * 32768 + 4096 + 4096;
    cudaFuncSetAttribute(knn_mma_kernel, cudaFuncAttributeMaxDynamicSharedMemorySize, SMEM);

    prep_all_kernel<<<1586, 256>>>(mem2, mem3, icov2, icov3, mean2, mean3);

    dim3 gk(NPIX / 64, 3);
    knn_mma_kernel<<<gk, 256, SMEM>>>(q2, q3);

    finalize_topk_kernel<<<16, 256>>>(out);
}

// round 15
// speedup vs baseline: 1.0013x; 1.0013x over previous
#include <cuda_runtime.h>
#include <cuda_bf16.h>
#include <math.h>
#include <stdint.h>

#define HW    784
#define NPIX  12544          // 16*28*28
#define MM    8192
#define FBIG  3.402823466e38f

// ---------------------------------------------------------------------------
// PTX helpers (sm_80+ family: ldmatrix / mma.sync / cp.async)
// ---------------------------------------------------------------------------
__device__ __forceinline__ uint32_t smem_u32(const void* p) {
    uint32_t a;
    asm("{ .reg .u64 t; cvta.to.shared.u64 t, %1; cvt.u32.u64 %0, t; }" : "=r"(a) : "l"(p));
    return a;
}
__device__ __forceinline__ void ldsm4(uint32_t* r, uint32_t a) {
    asm volatile("ldmatrix.sync.aligned.m8n8.x4.shared.b16 {%0,%1,%2,%3}, [%4];"
                 : "=r"(r[0]), "=r"(r[1]), "=r"(r[2]), "=r"(r[3]) : "r"(a));
}
__device__ __forceinline__ void mma16816(float* c, const uint32_t* a, const uint32_t* b) {
    asm volatile("mma.sync.aligned.m16n8k16.row.col.f32.bf16.bf16.f32 "
                 "{%0,%1,%2,%3},{%4,%5,%6,%7},{%8,%9},{%0,%1,%2,%3};"
                 : "+f"(c[0]), "+f"(c[1]), "+f"(c[2]), "+f"(c[3])
                 : "r"(a[0]), "r"(a[1]), "r"(a[2]), "r"(a[3]), "r"(b[0]), "r"(b[1]));
}
__device__ __forceinline__ void cpasync16(uint32_t dst, const void* src) {
    asm volatile("cp.async.cg.shared.global [%0], [%1], 16;" :: "r"(dst), "l"(src) : "memory");
}
#define CP_COMMIT() asm volatile("cp.async.commit_group;" ::: "memory")
#define CP_WAIT1()  asm volatile("cp.async.wait_group 1;"  ::: "memory")
#define CP_WAIT0()  asm volatile("cp.async.wait_group 0;"  ::: "memory")

// ---------------------------------------------------------------------------
// device scratch
// ---------------------------------------------------------------------------
__device__ float g_mnorm[2][MM];
__device__ float g_qnorm[2][NPIX];
__device__ float g_maha[2][NPIX];
__device__ float g_part[3][NPIX * 5];
__device__ float g_mahav[2][256];
__device__ float g_mahas0[2];
__device__ __align__(128) __nv_bfloat16 g_memb2[MM * 128];
__device__ __align__(128) __nv_bfloat16 g_memb3[MM * 256];
__device__ __align__(128) __nv_bfloat16 g_icovb2[256 * 128];
__device__ __align__(128) __nv_bfloat16 g_icovb3[256 * 256];

// ---------------- prep bodies (dispatched from one fat kernel) ----------------
template <int C, int LAYER>
__device__ __forceinline__ void prep_memb_body(const float* __restrict__ mem, int blk) {
    int i = blk * 256 + threadIdx.x;             // one i = 8 elements
    const float4 v0 = *reinterpret_cast<const float4*>(mem + (size_t)i * 8);
    const float4 v1 = *reinterpret_cast<const float4*>(mem + (size_t)i * 8 + 4);
    float s = v0.x * v0.x + v0.y * v0.y + v0.z * v0.z + v0.w * v0.w
            + v1.x * v1.x + v1.y * v1.y + v1.z * v1.z + v1.w * v1.w;
    __nv_bfloat16 t[8];
    t[0] = __float2bfloat16_rn(v0.x); t[1] = __float2bfloat16_rn(v0.y);
    t[2] = __float2bfloat16_rn(v0.z); t[3] = __float2bfloat16_rn(v0.w);
    t[4] = __float2bfloat16_rn(v1.x); t[5] = __float2bfloat16_rn(v1.y);
    t[6] = __float2bfloat16_rn(v1.z); t[7] = __float2bfloat16_rn(v1.w);
    __nv_bfloat16* dst = ((LAYER == 0) ? g_memb2 : g_memb3) + (size_t)i * 8;
    *reinterpret_cast<uint4*>(dst) = *reinterpret_cast<const uint4*>(t);
    const int SEG = C / 8;                       // 16 (C=128) or 32 (C=256)
#pragma unroll
    for (int o = SEG / 2; o; o >>= 1) s += __shfl_down_sync(0xffffffffu, s, o, SEG);
    if ((threadIdx.x & (SEG - 1)) == 0) g_mnorm[LAYER][i / SEG] = s;
}

template <int C, int LAYER>
__device__ __forceinline__ void prep_icov_body(const float* __restrict__ icov, int blk) {
    const int PER = C / 8;
    int i = blk * 256 + threadIdx.x;
    if (i >= 256 * PER) return;
    int col = i / PER, k0 = (i - col * PER) * 8;
    __nv_bfloat16 t[8];
    if (col < C) {
        const float* src = icov + (size_t)col * C + k0;
#pragma unroll
        for (int j = 0; j < 8; ++j) t[j] = __float2bfloat16_rn(src[j]);
    } else {
#pragma unroll
        for (int j = 0; j < 8; ++j) t[j] = __float2bfloat16_rn(0.f);
    }
    __nv_bfloat16* dst = ((LAYER == 0) ? g_icovb2 : g_icovb3) + (size_t)col * C + k0;
    *reinterpret_cast<uint4*>(dst) = *reinterpret_cast<const uint4*>(t);
}

template <int C, int LAYER>
__device__ __forceinline__ void prep_mahav_body(const float* __restrict__ icov,
                                                const float* __restrict__ mean,
                                                float* smean, float* red) {
    int c = threadIdx.x;                     // 256 threads
    if (c < C) smean[c] = mean[c];
    __syncthreads();
    float v = 0.f;
    if (c < C)
        for (int k = 0; k < C; ++k) v = fmaf(icov[(size_t)k * C + c], smean[k], v);
    g_mahav[LAYER][c] = (c < C) ? v : 0.f;
    red[c] = (c < C) ? v * smean[c] : 0.f;
    __syncthreads();
    for (int s = 128; s > 0; s >>= 1) {
        if (c < s) red[c] += red[c + s];
        __syncthreads();
    }
    if (c == 0) g_mahas0[LAYER] = red[0];
}

__global__ void prep_all_kernel(const float* __restrict__ mem2, const float* __restrict__ mem3,
                                const float* __restrict__ icov2, const float* __restrict__ icov3,
                                const float* __restrict__ mean2, const float* __restrict__ mean3) {
    __shared__ float smean[256];
    __shared__ float red[256];
    int bx = blockIdx.x;
    if (bx < 512)        prep_memb_body<128, 0>(mem2, bx);
    else if (bx < 1536)  prep_memb_body<256, 1>(mem3, bx - 512);
    else if (bx < 1552)  prep_icov_body<128, 0>(icov2, bx - 1536);
    else if (bx < 1584)  prep_icov_body<256, 1>(icov3, bx - 1552);
    else if (bx == 1584) prep_mahav_body<128, 0>(icov2, mean2, smean, red);
    else                 prep_mahav_body<256, 1>(icov3, mean3, smean, red);
}

// ---------------- sorted-5 insert (ascending, t[4] largest) ----------------
__device__ __forceinline__ void ins5(float* t, float v) {
    if (v < t[4]) {
#pragma unroll
        for (int u = 0; u < 5; ++u) {
            float c = t[u];
            float lo = fminf(c, v), hi = fmaxf(c, v);
            t[u] = lo; v = hi;
        }
    }
}

// ---------------------------------------------------------------------------
// knn GEMM body: 64 rows x MSPAN cols via mma.sync, fused top-5 + maha
// block = 256 threads = 8 warps (2 row-bands x 4 col-warps), warp tile 32x64
// stage = 256 cols x 64k (32KB), ring-2, 2 CTAs/SM
// stage loop order: wait -> sync -> mma -> sync -> issue(s+2) -> fold
// (fold touches only regs/smA/__ldg, never smB, so it overlaps the transfer)
// ---------------------------------------------------------------------------
template <int C, int LAYER, int SPLIT, int MSPAN, int DO_MAHA>
__device__ __forceinline__ void knn_body(const float* __restrict__ q,
                                         const __nv_bfloat16* __restrict__ gb,
                                         const __nv_bfloat16* __restrict__ icb,
                                         int colbase, char* sm) {
    constexpr int KTPC = C / 64;                 // k-tiles (of 64) per chunk
    constexpr int NSTN = (MSPAN / 256) * KTPC;   // normal stages (=64)
    constexpr int NSTT = NSTN + (DO_MAHA ? KTPC : 0);
    char* smA   = sm;                            // 64 x C bf16, swizzled
    char* smB   = sm + C * 128;                  // 2 x 32KB ring
    float* qp   = (float*)(sm + C * 128 + 65536);    // 16 x 64
    float* mh   = qp + 1024;                         // 64 x 16 maha partials

    const int tid  = threadIdx.x;
    const int lane = tid & 31, wid = tid >> 5;
    const int wr = wid >> 2, wc = wid & 3;
    const int row0 = blockIdx.x * 64;

    const uint32_t uA  = smem_u32(smA);
    const uint32_t uBb = smem_u32(smB);

    auto issue = [&](int s) {
        const __nv_bfloat16* srcb;
        if (s < NSTN) {
            const int ch = s / KTPC, kt = s - ch * KTPC;
            srcb = gb + (size_t)(colbase + ch * 256) * C + kt * 64;
        } else {
            srcb = icb + (size_t)(s - NSTN) * 64;        // icov chunk
        }
        const uint32_t db = uBb + (s & 1) * 32768;
#pragma unroll
        for (int j = 0; j < 8; ++j) {
            int id = tid + 256 * j;
            int ncol = id >> 3, kk = (id & 7) * 8;
            cpasync16(db + ncol * 128 + ((kk * 2) ^ ((ncol & 7) << 4)),
                      srcb + (size_t)ncol * C + kk);
        }
        CP_COMMIT();
    };

    issue(0); issue(1);                          // B streams during A gather

    // ---- A load: float4 along pixels (784%4==0 -> never crosses image) ----
    {
        const int r4 = (tid & 15) * 4;           // 4-row group (16 groups = 64 rows)
        const int cg = tid >> 4;                 // 16 channel groups
        float qn[4] = {0.f, 0.f, 0.f, 0.f};
        const int n = row0 + r4, b = n / HW, p = n - b * HW;
#pragma unroll 4
        for (int c = cg; c < C; c += 16) {
            const float4 v = *reinterpret_cast<const float4*>(q + ((size_t)b * C + c) * HW + p);
            qn[0] = fmaf(v.x, v.x, qn[0]); qn[1] = fmaf(v.y, v.y, qn[1]);
            qn[2] = fmaf(v.z, v.z, qn[2]); qn[3] = fmaf(v.w, v.w, qn[3]);
            const float vv[4] = {v.x, v.y, v.z, v.w};
#pragma unroll
            for (int j = 0; j < 4; ++j)
                *reinterpret_cast<__nv_bfloat16*>(smA + (r4 + j) * (C * 2) +
                    ((c * 2) ^ (((r4 + j) & 7) << 4))) = __float2bfloat16_rn(vv[j]);
        }
#pragma unroll
        for (int j = 0; j < 4; ++j) qp[cg * 64 + r4 + j] = qn[j];
    }
    __syncthreads();

    // ---- fragment address bases ----
    const uint32_t sw = (lane & 7) << 4;
    uint32_t aRow[2];
#pragma unroll
    for (int mi = 0; mi < 2; ++mi)
        aRow[mi] = uA + (wr * 32 + mi * 16 + (lane & 15)) * (C * 2);
    const uint32_t aKx = (lane >> 4) << 4;
    const uint32_t bCol = (uint32_t)(wc * 64 + ((lane >> 4) << 3) + (lane & 7));
    const uint32_t bKh  = ((lane >> 3) & 1) << 4;

    float acc[2][8][4];
#pragma unroll
    for (int mi = 0; mi < 2; ++mi)
#pragma unroll
        for (int ni = 0; ni < 8; ++ni)
#pragma unroll
            for (int e = 0; e < 4; ++e) acc[mi][ni][e] = 0.f;
    float t5[2][2][5];
#pragma unroll
    for (int mi = 0; mi < 2; ++mi)
#pragma unroll
        for (int h = 0; h < 2; ++h)
#pragma unroll
            for (int s = 0; s < 5; ++s) t5[mi][h][s] = FBIG;
    float mm[2][2] = {{0.f, 0.f}, {0.f, 0.f}};   // maha partials

    auto qrd = [&](int rl, int c) -> float {
        int cc = (c < C) ? c : (C - 1);
        uint16_t hbits = *reinterpret_cast<const uint16_t*>(
            smA + rl * (C * 2) + ((cc * 2) ^ ((rl & 7) << 4)));
        __nv_bfloat16 bh = *reinterpret_cast<__nv_bfloat16*>(&hbits);
        return __bfloat162float(bh);
    };

    for (int s = 0; s < NSTT; ++s) {
        if (s == NSTT - 1) CP_WAIT0(); else CP_WAIT1();
        __syncthreads();                     // stage s data visible to all
        const int kt = s % KTPC;
        const uint32_t db = uBb + (s & 1) * 32768;
#pragma unroll
        for (int ks = 0; ks < 4; ++ks) {
            uint32_t a[2][4];
            const uint32_t kbA = (uint32_t)(kt * 128 + ks * 32) + aKx;
#pragma unroll
            for (int mi = 0; mi < 2; ++mi) ldsm4(a[mi], aRow[mi] + (kbA ^ sw));
            const uint32_t kbB = (uint32_t)(ks * 32) + bKh;
#pragma unroll
            for (int nj = 0; nj < 4; ++nj) {
                uint32_t b[4];
                ldsm4(b, db + (bCol + nj * 16) * 128 + (kbB ^ sw));
#pragma unroll
                for (int mi = 0; mi < 2; ++mi) {
                    mma16816(acc[mi][nj * 2],     a[mi], b);
                    mma16816(acc[mi][nj * 2 + 1], a[mi], b + 2);
                }
            }
        }
        __syncthreads();                     // all warps done reading slot s&1
        if (s + 2 < NSTT) issue(s + 2);      // start next transfer BEFORE fold
        if (kt == KTPC - 1) {
            if (s < NSTN) {                  // normal chunk: fold into top-5
                const int ch = s / KTPC;
                const int cb = colbase + ch * 256 + wc * 64 + 2 * (lane & 3);
#pragma unroll
                for (int ni = 0; ni < 8; ++ni) {
                    const float mn0 = __ldg(&g_mnorm[LAYER][cb + ni * 8]);
                    const float mn1 = __ldg(&g_mnorm[LAYER][cb + ni * 8 + 1]);
#pragma unroll
                    for (int mi = 0; mi < 2; ++mi) {
                        ins5(t5[mi][0], fmaf(-2.f, acc[mi][ni][0], mn0));
                        ins5(t5[mi][0], fmaf(-2.f, acc[mi][ni][1], mn1));
                        ins5(t5[mi][1], fmaf(-2.f, acc[mi][ni][2], mn0));
                        ins5(t5[mi][1], fmaf(-2.f, acc[mi][ni][3], mn1));
                        acc[mi][ni][0] = 0.f; acc[mi][ni][1] = 0.f;
                        acc[mi][ni][2] = 0.f; acc[mi][ni][3] = 0.f;
                    }
                }
            } else if (DO_MAHA) {            // icov chunk: maha partials
                const int mcb = wc * 64 + 2 * (lane & 3);
#pragma unroll
                for (int ni = 0; ni < 8; ++ni) {
                    const int c0 = mcb + ni * 8, c1 = c0 + 1;
                    const float v0 = __ldg(&g_mahav[LAYER][c0]);
                    const float v1 = __ldg(&g_mahav[LAYER][c1]);
#pragma unroll
                    for (int mi = 0; mi < 2; ++mi) {
                        const int rl0 = wr * 32 + mi * 16 + (lane >> 2);
                        const int rl1 = rl0 + 8;
                        mm[mi][0] += (acc[mi][ni][0] - 2.f * v0) * qrd(rl0, c0)
                                   + (acc[mi][ni][1] - 2.f * v1) * qrd(rl0, c1);
                        mm[mi][1] += (acc[mi][ni][2] - 2.f * v0) * qrd(rl1, c0)
                                   + (acc[mi][ni][3] - 2.f * v1) * qrd(rl1, c1);
                    }
                }
            }
        }
    }

    // ---- per-row merges (smem aliasing: A/B region now free) ----
    __syncthreads();
    float* mg = (float*)sm;                  // 64 x 80 floats
#pragma unroll
    for (int mi = 0; mi < 2; ++mi)
#pragma unroll
        for (int h = 0; h < 2; ++h) {
            int rl = wr * 32 + mi * 16 + (lane >> 2) + 8 * h;
            int slot = wc * 4 + (lane & 3);
#pragma unroll
            for (int u = 0; u < 5; ++u) mg[rl * 80 + slot * 5 + u] = t5[mi][h][u];
            if (DO_MAHA) mh[rl * 16 + slot] = mm[mi][h];
        }
    __syncthreads();
    if (tid < 64) {
        float* c = mg + tid * 80;
        for (int it = 0; it < 5; ++it) {
            float mv = FBIG; int mi2 = 0;
            for (int e = 0; e < 80; ++e) { float v = c[e]; if (v < mv) { mv = v; mi2 = e; } }
            c[mi2] = FBIG;
            g_part[SPLIT][(size_t)(row0 + tid) * 5 + it] = mv;
        }
        if (SPLIT <= 1) {
            float qn = 0.f;
#pragma unroll
            for (int k = 0; k < 16; ++k) qn += qp[k * 64 + tid];
            g_qnorm[LAYER][row0 + tid] = qn;
        }
        if (DO_MAHA) {
            float s = __ldg(&g_mahas0[LAYER]);
#pragma unroll
            for (int e = 0; e < 16; ++e) s += mh[tid * 16 + e];
            g_maha[LAYER][row0 + tid] = sqrtf(fmaxf(s, 1e-12f));
        }
    }
}

__global__ __launch_bounds__(256, 2)
void knn_mma_kernel(const float* __restrict__ q2, const float* __restrict__ q3) {
    extern __shared__ char sm[];
    if (blockIdx.y == 0)
        knn_body<128, 0, 0, 8192, 1>(q2, g_memb2, g_icovb2, 0,    sm);
    else if (blockIdx.y == 1)
        knn_body<256, 1, 1, 4096, 1>(q3, g_memb3, g_icovb3, 0,    sm);
    else
        knn_body<256, 1, 2, 4096, 0>(q3, g_memb3, g_icovb3, 4096, sm);
}

// ---------------- finalize knn scores + combine maps -> d_out ----------------
__global__ void finalize_combine_kernel(float* __restrict__ out) {
    int n = blockIdx.x * blockDim.x + threadIdx.x;
    if (n >= NPIX) return;
    float knn0, knn1;
    {
        float qn = g_qnorm[0][n], sum = 0.f;
#pragma unroll
        for (int t = 0; t < 5; ++t)
            sum += sqrtf(fmaxf(g_part[0][(size_t)n * 5 + t] + qn, 1e-12f));
        knn0 = sum * 0.2f;
    }
    {
        float v[10];
#pragma unroll
        for (int t = 0; t < 5; ++t) {
            v[t]     = g_part[1][(size_t)n * 5 + t];
            v[5 + t] = g_part[2][(size_t)n * 5 + t];
        }
        float qn = g_qnorm[1][n], sum = 0.f;
        for (int it = 0; it < 5; ++it) {
            float mv = FBIG; int mi = 0;
#pragma unroll
            for (int e = 0; e < 10; ++e) if (v[e] < mv) { mv = v[e]; mi = e; }
            v[mi] = FBIG;
            sum += sqrtf(fmaxf(mv + qn, 1e-12f));
        }
        knn1 = sum * 0.2f;
    }
    float m2 = 0.5f * (knn0 + g_maha[0][n]);
    float m3 = 0.5f * (knn1 + g_maha[1][n]);
    out[16 + n]            = 0.5f * (m2 + m3);
    out[16 + NPIX + n]     = m2;
    out[16 + 2 * NPIX + n] = m3;
}

// ---------------- per-image top-10 mean (warp-parallel merge) ----------------
__global__ void topk_kernel(float* __restrict__ out) {
    int b = blockIdx.x, lane = threadIdx.x;
    const float* cm = out + 16 + (size_t)b * HW;
    float t[10];
#pragma unroll
    for (int s = 0; s < 10; ++s) t[s] = -FBIG;   // ascending, t[0] = min of kept
    for (int p = lane; p < HW; p += 32) {
        float v = cm[p];
        if (v > t[0]) {
            t[0] = v;
#pragma unroll
            for (int s = 0; s < 9; ++s) {
                float a = t[s], c = t[s + 1];
                t[s] = fminf(a, c); t[s + 1] = fmaxf(a, c);
            }
        }
    }
    int pos = 9;
    float sum = 0.f;
    for (int it = 0; it < 10; ++it) {
        float best = (pos >= 0) ? t[pos] : -FBIG;
        int   bl   = lane;
#pragma unroll
        for (int o = 16; o; o >>= 1) {
            float ov = __shfl_xor_sync(0xffffffffu, best, o);
            int   ol = __shfl_xor_sync(0xffffffffu, bl, o);
            if (ov > best || (ov == best && ol < bl)) { best = ov; bl = ol; }
        }
        sum += best;
        if (lane == bl) --pos;
    }
    if (lane == 0) out[b] = sum * 0.1f;
}

// ---------------- launch ----------------
extern "C" void kernel_launch(void* const* d_in, const int* in_sizes, int n_in,
                              void* d_out, int out_size) {
    const float* q2    = (const float*)d_in[0];
    const float* q3    = (const float*)d_in[1];
    const float* mem2  = (const float*)d_in[2];
    const float* mem3  = (const float*)d_in[3];
    const float* mean2 = (const float*)d_in[4];
    const float* mean3 = (const float*)d_in[5];
    const float* icov2 = (const float*)d_in[6];
    const float* icov3 = (const float*)d_in[7];
    float* out = (float*)d_out;

    // dyn smem (C=256): A 32KB + B ring 2x32KB + qp 4KB + mh 4KB = 106496
    const int SMEM = 256 * 128 + 2 * 32768 + 4096 + 4096;
    cudaFuncSetAttribute(knn_mma_kernel, cudaFuncAttributeMaxDynamicSharedMemorySize, SMEM);

    prep_all_kernel<<<1586, 256>>>(mem2, mem3, icov2, icov3, mean2, mean3);

    dim3 gk(NPIX / 64, 3);
    knn_mma_kernel<<<gk, 256, SMEM>>>(q2, q3);

    finalize_combine_kernel<<<(NPIX + 255) / 256, 256>>>(out);
    topk_kernel<<<16, 32>>>(out);
}

// round 16
// speedup vs baseline: 1.0095x; 1.0082x over previous
#include <cuda_runtime.h>
#include <cuda_bf16.h>
#include <math.h>
#include <stdint.h>

#define HW    784
#define NPIX  12544          // 16*28*28
#define MM    8192
#define FBIG  3.402823466e38f

// ---------------------------------------------------------------------------
// PTX helpers (sm_80+ family: ldmatrix / mma.sync / cp.async)
// ---------------------------------------------------------------------------
__device__ __forceinline__ uint32_t smem_u32(const void* p) {
    uint32_t a;
    asm("{ .reg .u64 t; cvta.to.shared.u64 t, %1; cvt.u32.u64 %0, t; }" : "=r"(a) : "l"(p));
    return a;
}
__device__ __forceinline__ void ldsm4(uint32_t* r, uint32_t a) {
    asm volatile("ldmatrix.sync.aligned.m8n8.x4.shared.b16 {%0,%1,%2,%3}, [%4];"
                 : "=r"(r[0]), "=r"(r[1]), "=r"(r[2]), "=r"(r[3]) : "r"(a));
}
__device__ __forceinline__ void mma16816(float* c, const uint32_t* a, const uint32_t* b) {
    asm volatile("mma.sync.aligned.m16n8k16.row.col.f32.bf16.bf16.f32 "
                 "{%0,%1,%2,%3},{%4,%5,%6,%7},{%8,%9},{%0,%1,%2,%3};"
                 : "+f"(c[0]), "+f"(c[1]), "+f"(c[2]), "+f"(c[3])
                 : "r"(a[0]), "r"(a[1]), "r"(a[2]), "r"(a[3]), "r"(b[0]), "r"(b[1]));
}
__device__ __forceinline__ void cpasync16(uint32_t dst, const void* src) {
    asm volatile("cp.async.cg.shared.global [%0], [%1], 16;" :: "r"(dst), "l"(src) : "memory");
}
#define CP_COMMIT() asm volatile("cp.async.commit_group;" ::: "memory")
#define CP_WAIT1()  asm volatile("cp.async.wait_group 1;"  ::: "memory")
#define CP_WAIT0()  asm volatile("cp.async.wait_group 0;"  ::: "memory")

// ---------------------------------------------------------------------------
// device scratch
// ---------------------------------------------------------------------------
__device__ float g_mnorm[2][MM];
__device__ float g_qnorm[2][NPIX];
__device__ float g_maha[2][NPIX];
__device__ float g_part[3][NPIX * 5];
__device__ float g_mahav[2][256];
__device__ float g_mahas0[2];
__device__ __align__(128) __nv_bfloat16 g_memb2[MM * 128];
__device__ __align__(128) __nv_bfloat16 g_memb3[MM * 256];
__device__ __align__(128) __nv_bfloat16 g_icovb2[256 * 128];
__device__ __align__(128) __nv_bfloat16 g_icovb3[256 * 256];

// ---------------- prep bodies (dispatched from one fat kernel) ----------------
template <int C, int LAYER>
__device__ __forceinline__ void prep_memb_body(const float* __restrict__ mem, int blk) {
    int i = blk * 256 + threadIdx.x;             // one i = 8 elements
    const float4 v0 = *reinterpret_cast<const float4*>(mem + (size_t)i * 8);
    const float4 v1 = *reinterpret_cast<const float4*>(mem + (size_t)i * 8 + 4);
    float s = v0.x * v0.x + v0.y * v0.y + v0.z * v0.z + v0.w * v0.w
            + v1.x * v1.x + v1.y * v1.y + v1.z * v1.z + v1.w * v1.w;
    __nv_bfloat16 t[8];
    t[0] = __float2bfloat16_rn(v0.x); t[1] = __float2bfloat16_rn(v0.y);
    t[2] = __float2bfloat16_rn(v0.z); t[3] = __float2bfloat16_rn(v0.w);
    t[4] = __float2bfloat16_rn(v1.x); t[5] = __float2bfloat16_rn(v1.y);
    t[6] = __float2bfloat16_rn(v1.z); t[7] = __float2bfloat16_rn(v1.w);
    __nv_bfloat16* dst = ((LAYER == 0) ? g_memb2 : g_memb3) + (size_t)i * 8;
    *reinterpret_cast<uint4*>(dst) = *reinterpret_cast<const uint4*>(t);
    const int SEG = C / 8;                       // 16 (C=128) or 32 (C=256)
#pragma unroll
    for (int o = SEG / 2; o; o >>= 1) s += __shfl_down_sync(0xffffffffu, s, o, SEG);
    if ((threadIdx.x & (SEG - 1)) == 0) g_mnorm[LAYER][i / SEG] = s;
}

template <int C, int LAYER>
__device__ __forceinline__ void prep_icov_body(const float* __restrict__ icov, int blk) {
    const int PER = C / 8;
    int i = blk * 256 + threadIdx.x;
    if (i >= 256 * PER) return;
    int col = i / PER, k0 = (i - col * PER) * 8;
    __nv_bfloat16 t[8];
    if (col < C) {
        const float* src = icov + (size_t)col * C + k0;
#pragma unroll
        for (int j = 0; j < 8; ++j) t[j] = __float2bfloat16_rn(src[j]);
    } else {
#pragma unroll
        for (int j = 0; j < 8; ++j) t[j] = __float2bfloat16_rn(0.f);
    }
    __nv_bfloat16* dst = ((LAYER == 0) ? g_icovb2 : g_icovb3) + (size_t)col * C + k0;
    *reinterpret_cast<uint4*>(dst) = *reinterpret_cast<const uint4*>(t);
}

template <int C, int LAYER>
__device__ __forceinline__ void prep_mahav_body(const float* __restrict__ icov,
                                                const float* __restrict__ mean,
                                                float* smean, float* red) {
    int c = threadIdx.x;                     // 256 threads
    if (c < C) smean[c] = mean[c];
    __syncthreads();
    float v = 0.f;
    if (c < C)
        for (int k = 0; k < C; ++k) v = fmaf(icov[(size_t)k * C + c], smean[k], v);
    g_mahav[LAYER][c] = (c < C) ? v : 0.f;
    red[c] = (c < C) ? v * smean[c] : 0.f;
    __syncthreads();
    for (int s = 128; s > 0; s >>= 1) {
        if (c < s) red[c] += red[c + s];
        __syncthreads();
    }
    if (c == 0) g_mahas0[LAYER] = red[0];
}

__global__ void prep_all_kernel(const float* __restrict__ mem2, const float* __restrict__ mem3,
                                const float* __restrict__ icov2, const float* __restrict__ icov3,
                                const float* __restrict__ mean2, const float* __restrict__ mean3) {
    __shared__ float smean[256];
    __shared__ float red[256];
    int bx = blockIdx.x;
    if (bx < 512)        prep_memb_body<128, 0>(mem2, bx);
    else if (bx < 1536)  prep_memb_body<256, 1>(mem3, bx - 512);
    else if (bx < 1552)  prep_icov_body<128, 0>(icov2, bx - 1536);
    else if (bx < 1584)  prep_icov_body<256, 1>(icov3, bx - 1552);
    else if (bx == 1584) prep_mahav_body<128, 0>(icov2, mean2, smean, red);
    else                 prep_mahav_body<256, 1>(icov3, mean3, smean, red);
}

// ---------------- sorted-5 insert (ascending, t[4] largest) ----------------
__device__ __forceinline__ void ins5(float* t, float v) {
    if (v < t[4]) {
#pragma unroll
        for (int u = 0; u < 5; ++u) {
            float c = t[u];
            float lo = fminf(c, v), hi = fmaxf(c, v);
            t[u] = lo; v = hi;
        }
    }
}

// ---------------------------------------------------------------------------
// knn GEMM body: 64 rows x MSPAN cols via mma.sync, fused top-5 + maha
// block = 256 threads = 8 warps (2 row-bands x 4 col-warps), warp tile 32x64
// stage = 256 cols x 64k (32KB), ring-2, 2 CTAs/SM   (R13-proven loop order)
// ---------------------------------------------------------------------------
template <int C, int LAYER, int SPLIT, int MSPAN, int DO_MAHA>
__device__ __forceinline__ void knn_body(const float* __restrict__ q,
                                         const __nv_bfloat16* __restrict__ gb,
                                         const __nv_bfloat16* __restrict__ icb,
                                         int colbase, char* sm) {
    constexpr int KTPC = C / 64;                 // k-tiles (of 64) per chunk
    constexpr int NSTN = (MSPAN / 256) * KTPC;   // normal stages (=64)
    constexpr int NSTT = NSTN + (DO_MAHA ? KTPC : 0);
    char* smA   = sm;                            // 64 x C bf16, swizzled
    char* smB   = sm + C * 128;                  // 2 x 32KB ring
    float* qp   = (float*)(sm + C * 128 + 65536);    // 16 x 64
    float* mh   = qp + 1024;                         // 64 x 16 maha partials

    const int tid  = threadIdx.x;
    const int lane = tid & 31, wid = tid >> 5;
    const int wr = wid >> 2, wc = wid & 3;
    const int row0 = blockIdx.x * 64;

    const uint32_t uA  = smem_u32(smA);
    const uint32_t uBb = smem_u32(smB);

    auto issue = [&](int s) {
        const __nv_bfloat16* srcb;
        if (s < NSTN) {
            const int ch = s / KTPC, kt = s - ch * KTPC;
            srcb = gb + (size_t)(colbase + ch * 256) * C + kt * 64;
        } else {
            srcb = icb + (size_t)(s - NSTN) * 64;        // icov chunk
        }
        const uint32_t db = uBb + (s & 1) * 32768;
#pragma unroll
        for (int j = 0; j < 8; ++j) {
            int id = tid + 256 * j;
            int ncol = id >> 3, kk = (id & 7) * 8;
            cpasync16(db + ncol * 128 + ((kk * 2) ^ ((ncol & 7) << 4)),
                      srcb + (size_t)ncol * C + kk);
        }
        CP_COMMIT();
    };

    issue(0); issue(1);                          // B streams during A gather

    // ---- A load: float4 along pixels (784%4==0 -> never crosses image) ----
    {
        const int r4 = (tid & 15) * 4;           // 4-row group (16 groups = 64 rows)
        const int cg = tid >> 4;                 // 16 channel groups
        float qn[4] = {0.f, 0.f, 0.f, 0.f};
        const int n = row0 + r4, b = n / HW, p = n - b * HW;
#pragma unroll 4
        for (int c = cg; c < C; c += 16) {
            const float4 v = *reinterpret_cast<const float4*>(q + ((size_t)b * C + c) * HW + p);
            qn[0] = fmaf(v.x, v.x, qn[0]); qn[1] = fmaf(v.y, v.y, qn[1]);
            qn[2] = fmaf(v.z, v.z, qn[2]); qn[3] = fmaf(v.w, v.w, qn[3]);
            const float vv[4] = {v.x, v.y, v.z, v.w};
#pragma unroll
            for (int j = 0; j < 4; ++j)
                *reinterpret_cast<__nv_bfloat16*>(smA + (r4 + j) * (C * 2) +
                    ((c * 2) ^ (((r4 + j) & 7) << 4))) = __float2bfloat16_rn(vv[j]);
        }
#pragma unroll
        for (int j = 0; j < 4; ++j) qp[cg * 64 + r4 + j] = qn[j];
    }
    __syncthreads();

    // ---- fragment address bases ----
    const uint32_t sw = (lane & 7) << 4;
    uint32_t aRow[2];
#pragma unroll
    for (int mi = 0; mi < 2; ++mi)
        aRow[mi] = uA + (wr * 32 + mi * 16 + (lane & 15)) * (C * 2);
    const uint32_t aKx = (lane >> 4) << 4;
    const uint32_t bCol = (uint32_t)(wc * 64 + ((lane >> 4) << 3) + (lane & 7));
    const uint32_t bKh  = ((lane >> 3) & 1) << 4;

    float acc[2][8][4];
#pragma unroll
    for (int mi = 0; mi < 2; ++mi)
#pragma unroll
        for (int ni = 0; ni < 8; ++ni)
#pragma unroll
            for (int e = 0; e < 4; ++e) acc[mi][ni][e] = 0.f;
    float t5[2][2][5];
#pragma unroll
    for (int mi = 0; mi < 2; ++mi)
#pragma unroll
        for (int h = 0; h < 2; ++h)
#pragma unroll
            for (int s = 0; s < 5; ++s) t5[mi][h][s] = FBIG;
    float mm[2][2] = {{0.f, 0.f}, {0.f, 0.f}};   // maha partials

    auto qrd = [&](int rl, int c) -> float {
        int cc = (c < C) ? c : (C - 1);
        uint16_t hbits = *reinterpret_cast<const uint16_t*>(
            smA + rl * (C * 2) + ((cc * 2) ^ ((rl & 7) << 4)));
        __nv_bfloat16 bh = *reinterpret_cast<__nv_bfloat16*>(&hbits);
        return __bfloat162float(bh);
    };

    for (int s = 0; s < NSTT; ++s) {
        if (s == NSTT - 1) CP_WAIT0(); else CP_WAIT1();
        __syncthreads();                     // stage s data visible to all
        const int kt = s % KTPC;
        const uint32_t db = uBb + (s & 1) * 32768;
#pragma unroll
        for (int ks = 0; ks < 4; ++ks) {
            uint32_t a[2][4];
            const uint32_t kbA = (uint32_t)(kt * 128 + ks * 32) + aKx;
#pragma unroll
            for (int mi = 0; mi < 2; ++mi) ldsm4(a[mi], aRow[mi] + (kbA ^ sw));
            const uint32_t kbB = (uint32_t)(ks * 32) + bKh;
#pragma unroll
            for (int nj = 0; nj < 4; ++nj) {
                uint32_t b[4];
                ldsm4(b, db + (bCol + nj * 16) * 128 + (kbB ^ sw));
#pragma unroll
                for (int mi = 0; mi < 2; ++mi) {
                    mma16816(acc[mi][nj * 2],     a[mi], b);
                    mma16816(acc[mi][nj * 2 + 1], a[mi], b + 2);
                }
            }
        }
        if (kt == KTPC - 1) {
            if (s < NSTN) {                  // normal chunk: fold into top-5
                const int ch = s / KTPC;
                const int cb = colbase + ch * 256 + wc * 64 + 2 * (lane & 3);
#pragma unroll
                for (int ni = 0; ni < 8; ++ni) {
                    const float mn0 = __ldg(&g_mnorm[LAYER][cb + ni * 8]);
                    const float mn1 = __ldg(&g_mnorm[LAYER][cb + ni * 8 + 1]);
#pragma unroll
                    for (int mi = 0; mi < 2; ++mi) {
                        ins5(t5[mi][0], fmaf(-2.f, acc[mi][ni][0], mn0));
                        ins5(t5[mi][0], fmaf(-2.f, acc[mi][ni][1], mn1));
                        ins5(t5[mi][1], fmaf(-2.f, acc[mi][ni][2], mn0));
                        ins5(t5[mi][1], fmaf(-2.f, acc[mi][ni][3], mn1));
                        acc[mi][ni][0] = 0.f; acc[mi][ni][1] = 0.f;
                        acc[mi][ni][2] = 0.f; acc[mi][ni][3] = 0.f;
                    }
                }
            } else if (DO_MAHA) {            // icov chunk: maha partials
                const int mcb = wc * 64 + 2 * (lane & 3);
#pragma unroll
                for (int ni = 0; ni < 8; ++ni) {
                    const int c0 = mcb + ni * 8, c1 = c0 + 1;
                    const float v0 = __ldg(&g_mahav[LAYER][c0]);
                    const float v1 = __ldg(&g_mahav[LAYER][c1]);
#pragma unroll
                    for (int mi = 0; mi < 2; ++mi) {
                        const int rl0 = wr * 32 + mi * 16 + (lane >> 2);
                        const int rl1 = rl0 + 8;
                        mm[mi][0] += (acc[mi][ni][0] - 2.f * v0) * qrd(rl0, c0)
                                   + (acc[mi][ni][1] - 2.f * v1) * qrd(rl0, c1);
                        mm[mi][1] += (acc[mi][ni][2] - 2.f * v0) * qrd(rl1, c0)
                                   + (acc[mi][ni][3] - 2.f * v1) * qrd(rl1, c1);
                    }
                }
            }
        }
        __syncthreads();                     // all warps done reading slot s&1
        if (s + 2 < NSTT) issue(s + 2);      // refill freed slot
    }

    // ---- per-row merges (smem aliasing: A/B region now free) ----
    __syncthreads();
    float* mg = (float*)sm;                  // 64 x 80 floats
#pragma unroll
    for (int mi = 0; mi < 2; ++mi)
#pragma unroll
        for (int h = 0; h < 2; ++h) {
            int rl = wr * 32 + mi * 16 + (lane >> 2) + 8 * h;
            int slot = wc * 4 + (lane & 3);
#pragma unroll
            for (int u = 0; u < 5; ++u) mg[rl * 80 + slot * 5 + u] = t5[mi][h][u];
            if (DO_MAHA) mh[rl * 16 + slot] = mm[mi][h];
        }
    __syncthreads();
    if (tid < 64) {
        float* c = mg + tid * 80;
        for (int it = 0; it < 5; ++it) {
            float mv = FBIG; int mi2 = 0;
            for (int e = 0; e < 80; ++e) { float v = c[e]; if (v < mv) { mv = v; mi2 = e; } }
            c[mi2] = FBIG;
            g_part[SPLIT][(size_t)(row0 + tid) * 5 + it] = mv;
        }
        if (SPLIT <= 1) {
            float qn = 0.f;
#pragma unroll
            for (int k = 0; k < 16; ++k) qn += qp[k * 64 + tid];
            g_qnorm[LAYER][row0 + tid] = qn;
        }
        if (DO_MAHA) {
            float s = __ldg(&g_mahas0[LAYER]);
#pragma unroll
            for (int e = 0; e < 16; ++e) s += mh[tid * 16 + e];
            g_maha[LAYER][row0 + tid] = sqrtf(fmaxf(s, 1e-12f));
        }
    }
}

__global__ __launch_bounds__(256, 2)
void knn_mma_kernel(const float* __restrict__ q2, const float* __restrict__ q3) {
    extern __shared__ char sm[];
    if (blockIdx.y == 0)
        knn_body<128, 0, 0, 8192, 1>(q2, g_memb2, g_icovb2, 0,    sm);
    else if (blockIdx.y == 1)
        knn_body<256, 1, 1, 4096, 1>(q3, g_memb3, g_icovb3, 0,    sm);
    else
        knn_body<256, 1, 2, 4096, 0>(q3, g_memb3, g_icovb3, 4096, sm);
}

// ---------------- finalize knn scores + combine maps -> d_out ----------------
__global__ void finalize_combine_kernel(float* __restrict__ out) {
    int n = blockIdx.x * blockDim.x + threadIdx.x;
    if (n >= NPIX) return;
    float knn0, knn1;
    {
        float qn = g_qnorm[0][n], sum = 0.f;
#pragma unroll
        for (int t = 0; t < 5; ++t)
            sum += sqrtf(fmaxf(g_part[0][(size_t)n * 5 + t] + qn, 1e-12f));
        knn0 = sum * 0.2f;
    }
    {
        float v[10];
#pragma unroll
        for (int t = 0; t < 5; ++t) {
            v[t]     = g_part[1][(size_t)n * 5 + t];
            v[5 + t] = g_part[2][(size_t)n * 5 + t];
        }
        float qn = g_qnorm[1][n], sum = 0.f;
        for (int it = 0; it < 5; ++it) {
            float mv = FBIG; int mi = 0;
#pragma unroll
            for (int e = 0; e < 10; ++e) if (v[e] < mv) { mv = v[e]; mi = e; }
            v[mi] = FBIG;
            sum += sqrtf(fmaxf(mv + qn, 1e-12f));
        }
        knn1 = sum * 0.2f;
    }
    float m2 = 0.5f * (knn0 + g_maha[0][n]);
    float m3 = 0.5f * (knn1 + g_maha[1][n]);
    out[16 + n]            = 0.5f * (m2 + m3);
    out[16 + NPIX + n]     = m2;
    out[16 + 2 * NPIX + n] = m3;
}

// ---------------- per-image top-10 mean: 8 warps scan + 2-level merge -------
__global__ void topk_kernel(float* __restrict__ out) {
    __shared__ float wtop[80];                   // 8 warps x 10
    const int b = blockIdx.x, tid = threadIdx.x;
    const int lane = tid & 31, w = tid >> 5;
    const float* cm = out + 16 + (size_t)b * HW;

    // each lane sees <= 4 pixels: keep ALL of them (sorted-4, ascending)
    float t[4];
#pragma unroll
    for (int s = 0; s < 4; ++s) t[s] = -FBIG;
    for (int p = tid; p < HW; p += 256) {
        float v = cm[p];
        if (v > t[0]) {
            t[0] = v;
#pragma unroll
            for (int s = 0; s < 3; ++s) {
                float a = t[s], c = t[s + 1];
                t[s] = fminf(a, c); t[s + 1] = fmaxf(a, c);
            }
        }
    }
    // per-warp argmax-10 pop -> wtop[w*10 + it]
    {
        int pos = 3;
        for (int it = 0; it < 10; ++it) {
            float best = (pos >= 0) ? t[pos] : -FBIG;
            int   bl   = lane;
#pragma unroll
            for (int o = 16; o; o >>= 1) {
                float ov = __shfl_xor_sync(0xffffffffu, best, o);
                int   ol = __shfl_xor_sync(0xffffffffu, bl, o);
                if (ov > best || (ov == best && ol < bl)) { best = ov; bl = ol; }
            }
            if (lane == 0) wtop[w * 10 + it] = best;
            if (lane == bl) --pos;
        }
    }
    __syncthreads();
    if (w == 0) {                                // warp 0 merges 80 candidates
        float c[3];
        c[0] = wtop[lane];
        c[1] = wtop[lane + 32];
        c[2] = (lane < 16) ? wtop[lane + 64] : -FBIG;
        // sort ascending (3-element network)
        { float lo = fminf(c[0], c[1]), hi = fmaxf(c[0], c[1]); c[0] = lo; c[1] = hi; }
        { float lo = fminf(c[1], c[2]), hi = fmaxf(c[1], c[2]); c[1] = lo; c[2] = hi; }
        { float lo = fminf(c[0], c[1]), hi = fmaxf(c[0], c[1]); c[0] = lo; c[1] = hi; }
        int pos = 2;
        float sum = 0.f;
        for (int it = 0; it < 10; ++it) {
            float best = (pos >= 0) ? c[pos] : -FBIG;
            int   bl   = lane;
#pragma unroll
            for (int o = 16; o; o >>= 1) {
                float ov = __shfl_xor_sync(0xffffffffu, best, o);
                int   ol = __shfl_xor_sync(0xffffffffu, bl, o);
                if (ov > best || (ov == best && ol < bl)) { best = ov; bl = ol; }
            }
            sum += best;
            if (lane == bl) --pos;
        }
        if (lane == 0) out[b] = sum * 0.1f;
    }
}

// ---------------- launch ----------------
extern "C" void kernel_launch(void* const* d_in, const int* in_sizes, int n_in,
                              void* d_out, int out_size) {
    const float* q2    = (const float*)d_in[0];
    const float* q3    = (const float*)d_in[1];
    const float* mem2  = (const float*)d_in[2];
    const float* mem3  = (const float*)d_in[3];
    const float* mean2 = (const float*)d_in[4];
    const float* mean3 = (const float*)d_in[5];
    const float* icov2 = (const float*)d_in[6];
    const float* icov3 = (const float*)d_in[7];
    float* out = (float*)d_out;

    // dyn smem (C=256): A 32KB + B ring 2x32KB + qp 4KB + mh 4KB = 106496
    const int SMEM = 256 * 128 + 2 * 32768 + 4096 + 4096;
    cudaFuncSetAttribute(knn_mma_kernel, cudaFuncAttributeMaxDynamicSharedMemorySize, SMEM);

    prep_all_kernel<<<1586, 256>>>(mem2, mem3, icov2, icov3, mean2, mean3);

    dim3 gk(NPIX / 64, 3);
    knn_mma_kernel<<<gk, 256, SMEM>>>(q2, q3);

    finalize_combine_kernel<<<(NPIX + 255) / 256, 256>>>(out);
    topk_kernel<<<16, 256>>>(out);
}